// round 15
// baseline (speedup 1.0000x reference)
#include <cuda_runtime.h>
#include <math.h>

#define NB      8192
#define TSTEPS  50
#define NGROUP  4096
#define NBLK    296          // 2 * 148 SMs -> all blocks resident, balanced
// smem W layout (floats): addr = i0*868 + i1*72 + d*12 + i2
// 16B segments: i0 stride 217, i1 stride 18, d stride 3 -> 8 sub-lanes hit
// distinct bank-groups mod 8: {0,4,3,7,6,2,1,5}
#define W_FLOATS (12 * 868)          // 41664 B dynamic smem

#define PI_D 3.14159265358979323846

typedef unsigned long long ull;

// ---- packed f32x2 helpers (sm_100a) --------------------------------------
__device__ __forceinline__ ull pack2(float lo, float hi) {
    ull r; asm("mov.b64 %0, {%1, %2};" : "=l"(r) : "f"(lo), "f"(hi)); return r;
}
__device__ __forceinline__ void unpack2(ull v, float& lo, float& hi) {
    asm("mov.b64 {%0, %1}, %2;" : "=f"(lo), "=f"(hi) : "l"(v));
}
__device__ __forceinline__ float hadd2(ull v) {
    float lo, hi; asm("mov.b64 {%0, %1}, %2;" : "=f"(lo), "=f"(hi) : "l"(v));
    return lo + hi;
}
__device__ __forceinline__ ull mul2(ull a, ull b) {
    ull r; asm("mul.rn.f32x2 %0, %1, %2;" : "=l"(r) : "l"(a), "l"(b)); return r;
}
__device__ __forceinline__ void fma2(ull& acc, ull a, ull b) {
    asm("fma.rn.f32x2 %0, %1, %2, %0;" : "+l"(acc) : "l"(a), "l"(b));
}

// ---------------------------------------------------------------------------
// accel2: geodesic acceleration for TWO trajectories sharing each weight load.
// 8-lane group: lane covers i0 in [i0b,i0b+3), i1 in [i1b,i1b+6).
// Normalization folded into W. dim-1 basis pre-packed as duplicated f32x2.
// Tail accumulation packed: (gf,dA) and (dB,dC) f32x2 accumulators.
// Group reduction: 3-round shfl_xor butterfly on 9 values/traj.
// ---------------------------------------------------------------------------
__device__ __forceinline__ void accel2(
    const ulonglong2* __restrict__ Wd, int i0b, int i1b, unsigned gmask,
    float L0, float L1, float L2,
    float w10, float w11, float w12,
    const float pe[2][3], const float ve[2][3],
    float ac[2][3])
{
    ull s2p[2][6], c2p[2][6];
    ull s1p[2][6], c1p[2][6];        // duplicated (x,x) pairs, pre-packed
    float sk0[2], ck0[2], fr0[2], sa0[2], ca0[2];

    #pragma unroll
    for (int t = 0; t < 2; ++t) {
        // dim-2 basis: all 12 harmonics via angle-addition recurrence,
        // packed in (i2, i2+1) pairs.
        {
            float arg = w12 * (pe[t][2] + L2);
            float sa, ca; __sincosf(arg, &sa, &ca);
            float sk = sa, ck = ca, fr = w12;
            #pragma unroll
            for (int h = 0; h < 6; ++h) {
                float sA = sk, cA = ck * fr;
                float ns = sk * ca + ck * sa;
                float nc = ck * ca - sk * sa;
                float fr2 = fr + w12;
                float sB = ns, cB = nc * fr2;
                s2p[t][h] = pack2(sA, sB);
                c2p[t][h] = pack2(cA, cB);
                sk = ns * ca + nc * sa;
                ck = nc * ca - ns * sa;
                fr = fr2 + w12;
            }
        }
        // dim-1 basis: lane's 6 harmonics via recurrence, duplicated-pair pack
        {
            float arg = w11 * (pe[t][1] + L1);
            float sa, ca; __sincosf(arg, &sa, &ca);
            float fb = (float)(i1b + 1);
            float sk, ck; __sincosf(fb * arg, &sk, &ck);
            float fr = w11 * fb;
            #pragma unroll
            for (int j = 0; j < 6; ++j) {
                float cf = ck * fr;
                s1p[t][j] = pack2(sk, sk);
                c1p[t][j] = pack2(cf, cf);
                float ns = sk * ca + ck * sa;
                float nc = ck * ca - sk * sa;
                sk = ns; ck = nc; fr += w11;
            }
        }
        // dim-0 basis: 3-step recurrence state (consumed in the rolled ii loop)
        {
            float arg = w10 * (pe[t][0] + L0);
            float sa, ca; __sincosf(arg, &sa, &ca);
            float fb = (float)(i0b + 1);
            float sk, ck; __sincosf(fb * arg, &sk, &ck);
            sk0[t] = sk; ck0[t] = ck; fr0[t] = w10 * fb;
            sa0[t] = sa; ca0[t] = ca;
        }
    }

    // packed accumulators: lo=gf, hi=dA  /  lo=dB, hi=dC
    ull gfdA[2][6], dBdC[2][6];
    #pragma unroll
    for (int t = 0; t < 2; ++t)
        #pragma unroll
        for (int d = 0; d < 6; ++d) { gfdA[t][d] = 0ull; dBdC[t][d] = 0ull; }

    #pragma unroll 1
    for (int ii = 0; ii < 3; ++ii) {
        ull sc0[2], ss0[2];
        #pragma unroll
        for (int t = 0; t < 2; ++t) {
            float s0v = sk0[t];
            float c0v = ck0[t] * fr0[t];
            sc0[t] = pack2(s0v, c0v);
            ss0[t] = pack2(s0v, s0v);
            float ns = sk0[t] * ca0[t] + ck0[t] * sa0[t];
            float nc = ck0[t] * ca0[t] - sk0[t] * sa0[t];
            sk0[t] = ns; ck0[t] = nc; fr0[t] += w10;
        }
        const ulonglong2* __restrict__ Ri = Wd + i1b * 18 + (i0b + ii) * 217;
        #pragma unroll
        for (int d = 0; d < 6; ++d) {
            const ulonglong2* __restrict__ R = Ri + d * 3;
            ull uss[2], ucs[2], usc[2];
            #pragma unroll
            for (int j = 0; j < 6; ++j) {
                const ulonglong2* __restrict__ P = R + j * 18;
                ulonglong2 u0 = P[0], u1 = P[1], u2 = P[2];
                #pragma unroll
                for (int t = 0; t < 2; ++t) {
                    ull ts = mul2(u0.x, s2p[t][0]);
                    fma2(ts, u0.y, s2p[t][1]);
                    fma2(ts, u1.x, s2p[t][2]);
                    fma2(ts, u1.y, s2p[t][3]);
                    fma2(ts, u2.x, s2p[t][4]);
                    fma2(ts, u2.y, s2p[t][5]);
                    ull tc = mul2(u0.x, c2p[t][0]);
                    fma2(tc, u0.y, c2p[t][1]);
                    fma2(tc, u1.x, c2p[t][2]);
                    fma2(tc, u1.y, c2p[t][3]);
                    fma2(tc, u2.x, c2p[t][4]);
                    fma2(tc, u2.y, c2p[t][5]);
                    if (j == 0) {
                        uss[t] = mul2(ts, s1p[t][0]);
                        ucs[t] = mul2(ts, c1p[t][0]);
                        usc[t] = mul2(tc, s1p[t][0]);
                    } else {
                        fma2(uss[t], ts, s1p[t][j]);
                        fma2(ucs[t], ts, c1p[t][j]);
                        fma2(usc[t], tc, s1p[t][j]);
                    }
                }
            }
            #pragma unroll
            for (int t = 0; t < 2; ++t) {
                float us = hadd2(uss[t]), uc = hadd2(ucs[t]), uq = hadd2(usc[t]);
                fma2(gfdA[t][d], pack2(us, us), sc0[t]);   // gf += us*s0, dA += us*c0
                fma2(dBdC[t][d], pack2(uc, uq), ss0[t]);   // dB += uc*s0, dC += uq*s0
            }
        }
    }

    // ---- per-lane projection to h[3] (linear in dA/dB/dC) + reduction ----
    float gf[2][6], hv[2][3];
    #pragma unroll
    for (int t = 0; t < 2; ++t) {
        float dA[6], dB[6], dC[6];
        #pragma unroll
        for (int d = 0; d < 6; ++d) {
            unpack2(gfdA[t][d], gf[t][d], dA[d]);
            unpack2(dBdC[t][d], dB[d], dC[d]);
        }
        float vx = ve[t][0], vy = ve[t][1], vz = ve[t][2];
        float F0 = vx * dA[0] + vy * dB[0] + vz * dC[0];
        float F1 = vx * dA[1] + vy * dB[1] + vz * dC[1];
        float F2 = vx * dA[2] + vy * dB[2] + vz * dC[2];
        float F3 = vx * dA[3] + vy * dB[3] + vz * dC[3];
        float F4 = vx * dA[4] + vy * dB[4] + vz * dC[4];
        float F5 = vx * dA[5] + vy * dB[5] + vz * dC[5];
        float A0 = vx * F0 + vy * F1 + vz * F3;
        float A1 = vx * F1 + vy * F2 + vz * F4;
        float A2 = vx * F3 + vy * F4 + vz * F5;
        float xx = vx * vx, yy = vy * vy, zz = vz * vz;
        float xy = 2.f * vx * vy, xz = 2.f * vx * vz, yz = 2.f * vy * vz;
        float B0 = xx * dA[0] + yy * dA[2] + zz * dA[5] + xy * dA[1] + xz * dA[3] + yz * dA[4];
        float B1 = xx * dB[0] + yy * dB[2] + zz * dB[5] + xy * dB[1] + xz * dB[3] + yz * dB[4];
        float B2 = xx * dC[0] + yy * dC[2] + zz * dC[5] + xy * dC[1] + xz * dC[3] + yz * dC[4];
        hv[t][0] = 2.f * A0 - B0;
        hv[t][1] = 2.f * A1 - B1;
        hv[t][2] = 2.f * A2 - B2;
    }

    // ---- reduce 9 values per trajectory across the 8-lane group (masked) ----
    #pragma unroll
    for (int t = 0; t < 2; ++t)
        #pragma unroll
        for (int o = 1; o <= 4; o <<= 1) {
            #pragma unroll
            for (int d = 0; d < 6; ++d)
                gf[t][d] += __shfl_xor_sync(gmask, gf[t][d], o);
            #pragma unroll
            for (int c = 0; c < 3; ++c)
                hv[t][c] += __shfl_xor_sync(gmask, hv[t][c], o);
        }

    #pragma unroll
    for (int t = 0; t < 2; ++t) {
        float g00 = gf[t][0] + 1.f, g01 = gf[t][1], g11 = gf[t][2] + 1.f;
        float g02 = gf[t][3], g12 = gf[t][4], g22 = gf[t][5] + 1.f;
        float k00 = g11 * g22 - g12 * g12;
        float k01 = g02 * g12 - g01 * g22;
        float k02 = g01 * g12 - g02 * g11;
        float det = g00 * k00 + g01 * k01 + g02 * k02;
        float idet = 1.0f / det;
        float i00 = k00 * idet, i01 = k01 * idet, i02 = k02 * idet;
        float i11 = (g00 * g22 - g02 * g02) * idet;
        float i12 = (g01 * g02 - g00 * g12) * idet;
        float i22 = (g00 * g11 - g01 * g01) * idet;
        float h0 = hv[t][0], h1 = hv[t][1], h2 = hv[t][2];
        ac[t][0] = -0.5f * (i00 * h0 + i01 * h1 + i02 * h2);
        ac[t][1] = -0.5f * (i01 * h0 + i11 * h1 + i12 * h2);
        ac[t][2] = -0.5f * (i02 * h0 + i12 * h1 + i22 * h2);
    }
}

// ---------------------------------------------------------------------------
// Fused kernel: per-block prep (L, W into padded smem) + RK4 for 2 traj/group.
// 296 blocks x 128 threads; groups strided across blocks for SM balance:
// group = blockIdx.x + 296 * slot  (slot = tid/8). ~13.8 active groups/block.
// ---------------------------------------------------------------------------
__global__ void __launch_bounds__(128)
geo_kernel(const float* __restrict__ pos0, const float* __restrict__ vel0,
           const float* __restrict__ beta, const float* __restrict__ ls,
           const float* __restrict__ basis, float* __restrict__ out)
{
    extern __shared__ ulonglong2 Wd[];
    __shared__ float sprm[9];
    __shared__ float red[12];

    int tid = threadIdx.x;

    // ---- L = 1.5 * max|basis| per dim ----
    {
        float m0 = 0.f, m1 = 0.f, m2 = 0.f;
        for (int r = tid; r < 256; r += 128) {
            m0 = fmaxf(m0, fabsf(basis[r * 3 + 0]));
            m1 = fmaxf(m1, fabsf(basis[r * 3 + 1]));
            m2 = fmaxf(m2, fabsf(basis[r * 3 + 2]));
        }
        #pragma unroll
        for (int o = 16; o > 0; o >>= 1) {
            m0 = fmaxf(m0, __shfl_xor_sync(0xffffffffu, m0, o));
            m1 = fmaxf(m1, __shfl_xor_sync(0xffffffffu, m1, o));
            m2 = fmaxf(m2, __shfl_xor_sync(0xffffffffu, m2, o));
        }
        if ((tid & 31) == 0) {
            int w = tid >> 5;
            red[w * 3 + 0] = m0; red[w * 3 + 1] = m1; red[w * 3 + 2] = m2;
        }
        __syncthreads();
        if (tid == 0) {
            #pragma unroll
            for (int d = 0; d < 3; ++d) {
                float M = fmaxf(fmaxf(red[d], red[3 + d]), fmaxf(red[6 + d], red[9 + d]));
                float L = 1.5f * M;
                sprm[d]     = L;
                sprm[3 + d] = (float)(PI_D) / (2.0f * L);
                sprm[6 + d] = 1.0f / sqrtf(L);
            }
        }
        __syncthreads();
    }
    float L0 = sprm[0], L1 = sprm[1], L2 = sprm[2];
    float w10 = sprm[3], w11 = sprm[4], w12 = sprm[5];
    float isAll = sprm[6] * sprm[7] * sprm[8];   // folded into W below

    // ---- W into padded smem layout, normalization folded in ----
    {
        float* Wf = (float*)Wd;
        for (int idx = tid; idx < 10368; idx += 128) {
            int i2 = idx % 12;
            int d  = (idx / 12) % 6;
            int i1 = (idx / 72) % 12;
            int i0 = idx / 864;
            int m  = (i0 * 12 + i1) * 12 + i2;
            float ls0 = ls[d * 3 + 0], ls1 = ls[d * 3 + 1], ls2 = ls[d * 3 + 2];
            float q0 = w10 * (float)(i0 + 1);
            float q1 = w11 * (float)(i1 + 1);
            float q2 = w12 * (float)(i2 + 1);
            float e = -0.25f * (q0 * q0 * ls0 * ls0 + q1 * q1 * ls1 * ls1 + q2 * q2 * ls2 * ls2);
            float psd = 3.96850262992049984f * sqrtf(ls0 * ls1 * ls2) * expf(e);
            Wf[i0 * 868 + i1 * 72 + d * 12 + i2] = beta[d * 1728 + m] * psd * isAll;
        }
    }
    __syncthreads();

    // ---- integrate: 2 trajectories per 8-lane group, strided group ids ----
    int slot  = tid >> 3;
    int sub   = tid & 7;
    int group = blockIdx.x + NBLK * slot;
    if (group >= NGROUP) return;          // idle slots: no barriers below

    unsigned gmask = 0xFFu << ((tid & 31) & ~7);   // this 8-lane group's lanes

    int i0b = (sub >> 1) * 3;
    int i1b = (sub & 1) * 6;

    float p[2][3], v[2][3];
    #pragma unroll
    for (int t = 0; t < 2; ++t) {
        int b = group * 2 + t;
        p[t][0] = pos0[b * 3 + 0]; p[t][1] = pos0[b * 3 + 1]; p[t][2] = pos0[b * 3 + 2];
        v[t][0] = vel0[b * 3 + 0]; v[t][1] = vel0[b * 3 + 1]; v[t][2] = vel0[b * 3 + 2];
    }

    if (sub == 0) {
        #pragma unroll
        for (int t = 0; t < 2; ++t) {
            int b = group * 2 + t;
            float* op = out + (size_t)0 * NB * 3 + b * 3;
            float* ov = out + (size_t)1 * NB * 3 + b * 3;
            op[0] = p[t][0]; op[1] = p[t][1]; op[2] = p[t][2];
            ov[0] = v[t][0]; ov[1] = v[t][1]; ov[2] = v[t][2];
        }
    }

    const float dt  = (float)(1.0 / 49.0);
    const float hdt = (float)(0.5 * (1.0 / 49.0));
    const float dt6 = (float)((1.0 / 49.0) / 6.0);

    #pragma unroll 1
    for (int ts = 1; ts < TSTEPS; ++ts) {
        float pac[2][3], vac[2][3], dp[2][3], dv[2][3];
        #pragma unroll
        for (int t = 0; t < 2; ++t)
            #pragma unroll
            for (int c = 0; c < 3; ++c) {
                pac[t][c] = 0.f; vac[t][c] = 0.f; dp[t][c] = 0.f; dv[t][c] = 0.f;
            }
        #pragma unroll 1
        for (int s = 0; s < 4; ++s) {
            float pe[2][3], ve[2][3], ac[2][3];
            float cs = (s == 3) ? dt : hdt;
            #pragma unroll
            for (int t = 0; t < 2; ++t)
                #pragma unroll
                for (int c = 0; c < 3; ++c) {
                    if (s == 0) { pe[t][c] = p[t][c]; ve[t][c] = v[t][c]; }
                    else {
                        pe[t][c] = fmaf(cs, dp[t][c], p[t][c]);
                        ve[t][c] = fmaf(cs, dv[t][c], v[t][c]);
                    }
                }
            accel2(Wd, i0b, i1b, gmask, L0, L1, L2, w10, w11, w12,
                   pe, ve, ac);
            float w = (s == 0 || s == 3) ? 1.f : 2.f;
            #pragma unroll
            for (int t = 0; t < 2; ++t)
                #pragma unroll
                for (int c = 0; c < 3; ++c) {
                    dp[t][c] = ve[t][c]; dv[t][c] = ac[t][c];
                    pac[t][c] = fmaf(w, dp[t][c], pac[t][c]);
                    vac[t][c] = fmaf(w, dv[t][c], vac[t][c]);
                }
        }
        #pragma unroll
        for (int t = 0; t < 2; ++t)
            #pragma unroll
            for (int c = 0; c < 3; ++c) {
                p[t][c] = fmaf(dt6, pac[t][c], p[t][c]);
                v[t][c] = fmaf(dt6, vac[t][c], v[t][c]);
            }

        if (sub == 0) {
            #pragma unroll
            for (int t = 0; t < 2; ++t) {
                int b = group * 2 + t;
                float* op = out + ((size_t)(ts * 2 + 0) * NB + b) * 3;
                float* ov = out + ((size_t)(ts * 2 + 1) * NB + b) * 3;
                op[0] = p[t][0]; op[1] = p[t][1]; op[2] = p[t][2];
                ov[0] = v[t][0]; ov[1] = v[t][1]; ov[2] = v[t][2];
            }
        }
    }
}

// ---------------------------------------------------------------------------
extern "C" void kernel_launch(void* const* d_in, const int* in_sizes, int n_in,
                              void* d_out, int out_size) {
    const float* pos0  = (const float*)d_in[0];
    const float* vel0  = (const float*)d_in[1];
    const float* beta  = (const float*)d_in[2];
    const float* ls    = (const float*)d_in[3];
    const float* basis = (const float*)d_in[4];
    float* out = (float*)d_out;

    geo_kernel<<<NBLK, 128, W_FLOATS * 4>>>(pos0, vel0, beta, ls, basis, out);
}

// round 16
// speedup vs baseline: 1.0468x; 1.0468x over previous
#include <cuda_runtime.h>
#include <math.h>

#define NB      8192
#define TSTEPS  50
#define NGROUP  4096
#define NBLK    148          // 1 block per SM, dense warps, balanced groups
// smem W layout (floats): addr = i0*868 + i1*72 + d*12 + i2
// 16B segments: i0 stride 217, i1 stride 18, d stride 3 -> 8 sub-lanes hit
// distinct bank-groups mod 8: {0,4,3,7,6,2,1,5}
#define W_FLOATS (12 * 868)          // 41664 B dynamic smem

#define PI_D 3.14159265358979323846

typedef unsigned long long ull;

// ---- packed f32x2 helpers (sm_100a) --------------------------------------
__device__ __forceinline__ ull pack2(float lo, float hi) {
    ull r; asm("mov.b64 %0, {%1, %2};" : "=l"(r) : "f"(lo), "f"(hi)); return r;
}
__device__ __forceinline__ float hadd2(ull v) {
    float lo, hi; asm("mov.b64 {%0, %1}, %2;" : "=f"(lo), "=f"(hi) : "l"(v));
    return lo + hi;
}
__device__ __forceinline__ ull mul2(ull a, ull b) {
    ull r; asm("mul.rn.f32x2 %0, %1, %2;" : "=l"(r) : "l"(a), "l"(b)); return r;
}
__device__ __forceinline__ void fma2(ull& acc, ull a, ull b) {
    asm("fma.rn.f32x2 %0, %1, %2, %0;" : "+l"(acc) : "l"(a), "l"(b));
}

// ---------------------------------------------------------------------------
// accel2: geodesic acceleration for TWO trajectories sharing each weight load.
// 8-lane group: lane covers i0 in [i0b,i0b+3), i1 in [i1b,i1b+6).
// Normalization folded into W (smem fill). R12 core: scalar accumulators,
// inline s1/c1 packs, single 6-deep fma2 chains, masked shfl reduction.
// ---------------------------------------------------------------------------
__device__ __forceinline__ void accel2(
    const ulonglong2* __restrict__ Wd, int i0b, int i1b, unsigned gmask,
    float L0, float L1, float L2,
    float w10, float w11, float w12,
    const float pe[2][3], const float ve[2][3],
    float ac[2][3])
{
    ull   s2p[2][6], c2p[2][6];
    float s1[2][6],  c1[2][6];
    float sk0[2], ck0[2], fr0[2], sa0[2], ca0[2];

    #pragma unroll
    for (int t = 0; t < 2; ++t) {
        // dim-2 basis: all 12 harmonics via angle-addition recurrence,
        // packed in (i2, i2+1) pairs.
        {
            float arg = w12 * (pe[t][2] + L2);
            float sa, ca; __sincosf(arg, &sa, &ca);
            float sk = sa, ck = ca, fr = w12;
            #pragma unroll
            for (int h = 0; h < 6; ++h) {
                float sA = sk, cA = ck * fr;
                float ns = sk * ca + ck * sa;
                float nc = ck * ca - sk * sa;
                float fr2 = fr + w12;
                float sB = ns, cB = nc * fr2;
                s2p[t][h] = pack2(sA, sB);
                c2p[t][h] = pack2(cA, cB);
                sk = ns * ca + nc * sa;
                ck = nc * ca - ns * sa;
                fr = fr2 + w12;
            }
        }
        // dim-1 basis: lane's 6 harmonics via recurrence
        {
            float arg = w11 * (pe[t][1] + L1);
            float sa, ca; __sincosf(arg, &sa, &ca);
            float fb = (float)(i1b + 1);
            float sk, ck; __sincosf(fb * arg, &sk, &ck);
            float fr = w11 * fb;
            #pragma unroll
            for (int j = 0; j < 6; ++j) {
                s1[t][j] = sk;
                c1[t][j] = ck * fr;
                float ns = sk * ca + ck * sa;
                float nc = ck * ca - sk * sa;
                sk = ns; ck = nc; fr += w11;
            }
        }
        // dim-0 basis: 3-step recurrence state (consumed in the rolled ii loop)
        {
            float arg = w10 * (pe[t][0] + L0);
            float sa, ca; __sincosf(arg, &sa, &ca);
            float fb = (float)(i0b + 1);
            float sk, ck; __sincosf(fb * arg, &sk, &ck);
            sk0[t] = sk; ck0[t] = ck; fr0[t] = w10 * fb;
            sa0[t] = sa; ca0[t] = ca;
        }
    }

    float gf[2][6], dA[2][6], dB[2][6], dC[2][6];
    #pragma unroll
    for (int t = 0; t < 2; ++t)
        #pragma unroll
        for (int d = 0; d < 6; ++d) { gf[t][d] = 0.f; dA[t][d] = 0.f; dB[t][d] = 0.f; dC[t][d] = 0.f; }

    #pragma unroll 1
    for (int ii = 0; ii < 3; ++ii) {
        float s0v[2], c0v[2];
        #pragma unroll
        for (int t = 0; t < 2; ++t) {
            s0v[t] = sk0[t];
            c0v[t] = ck0[t] * fr0[t];
            float ns = sk0[t] * ca0[t] + ck0[t] * sa0[t];
            float nc = ck0[t] * ca0[t] - sk0[t] * sa0[t];
            sk0[t] = ns; ck0[t] = nc; fr0[t] += w10;
        }
        const ulonglong2* __restrict__ Ri = Wd + i1b * 18 + (i0b + ii) * 217;
        #pragma unroll
        for (int d = 0; d < 6; ++d) {
            const ulonglong2* __restrict__ R = Ri + d * 3;
            ull uss[2], ucs[2], usc[2];
            #pragma unroll
            for (int j = 0; j < 6; ++j) {
                const ulonglong2* __restrict__ P = R + j * 18;
                ulonglong2 u0 = P[0], u1 = P[1], u2 = P[2];
                #pragma unroll
                for (int t = 0; t < 2; ++t) {
                    ull ts = mul2(u0.x, s2p[t][0]);
                    fma2(ts, u0.y, s2p[t][1]);
                    fma2(ts, u1.x, s2p[t][2]);
                    fma2(ts, u1.y, s2p[t][3]);
                    fma2(ts, u2.x, s2p[t][4]);
                    fma2(ts, u2.y, s2p[t][5]);
                    ull tc = mul2(u0.x, c2p[t][0]);
                    fma2(tc, u0.y, c2p[t][1]);
                    fma2(tc, u1.x, c2p[t][2]);
                    fma2(tc, u1.y, c2p[t][3]);
                    fma2(tc, u2.x, c2p[t][4]);
                    fma2(tc, u2.y, c2p[t][5]);
                    ull ds1 = pack2(s1[t][j], s1[t][j]);
                    ull dc1 = pack2(c1[t][j], c1[t][j]);
                    if (j == 0) {
                        uss[t] = mul2(ts, ds1);
                        ucs[t] = mul2(ts, dc1);
                        usc[t] = mul2(tc, ds1);
                    } else {
                        fma2(uss[t], ts, ds1);
                        fma2(ucs[t], ts, dc1);
                        fma2(usc[t], tc, ds1);
                    }
                }
            }
            #pragma unroll
            for (int t = 0; t < 2; ++t) {
                float us = hadd2(uss[t]), uc = hadd2(ucs[t]), uq = hadd2(usc[t]);
                gf[t][d] = fmaf(us, s0v[t], gf[t][d]);
                dA[t][d] = fmaf(us, c0v[t], dA[t][d]);
                dB[t][d] = fmaf(uc, s0v[t], dB[t][d]);
                dC[t][d] = fmaf(uq, s0v[t], dC[t][d]);
            }
        }
    }

    // ---- per-lane projection to h[3] (linear in dA/dB/dC) ----
    float hv[2][3];
    #pragma unroll
    for (int t = 0; t < 2; ++t) {
        float vx = ve[t][0], vy = ve[t][1], vz = ve[t][2];
        float F0 = vx * dA[t][0] + vy * dB[t][0] + vz * dC[t][0];
        float F1 = vx * dA[t][1] + vy * dB[t][1] + vz * dC[t][1];
        float F2 = vx * dA[t][2] + vy * dB[t][2] + vz * dC[t][2];
        float F3 = vx * dA[t][3] + vy * dB[t][3] + vz * dC[t][3];
        float F4 = vx * dA[t][4] + vy * dB[t][4] + vz * dC[t][4];
        float F5 = vx * dA[t][5] + vy * dB[t][5] + vz * dC[t][5];
        float A0 = vx * F0 + vy * F1 + vz * F3;
        float A1 = vx * F1 + vy * F2 + vz * F4;
        float A2 = vx * F3 + vy * F4 + vz * F5;
        float xx = vx * vx, yy = vy * vy, zz = vz * vz;
        float xy = 2.f * vx * vy, xz = 2.f * vx * vz, yz = 2.f * vy * vz;
        float B0 = xx * dA[t][0] + yy * dA[t][2] + zz * dA[t][5] + xy * dA[t][1] + xz * dA[t][3] + yz * dA[t][4];
        float B1 = xx * dB[t][0] + yy * dB[t][2] + zz * dB[t][5] + xy * dB[t][1] + xz * dB[t][3] + yz * dB[t][4];
        float B2 = xx * dC[t][0] + yy * dC[t][2] + zz * dC[t][5] + xy * dC[t][1] + xz * dC[t][3] + yz * dC[t][4];
        hv[t][0] = 2.f * A0 - B0;
        hv[t][1] = 2.f * A1 - B1;
        hv[t][2] = 2.f * A2 - B2;
    }

    // ---- reduce 9 values per trajectory across the 8-lane group (masked) ----
    #pragma unroll
    for (int t = 0; t < 2; ++t)
        #pragma unroll
        for (int o = 1; o <= 4; o <<= 1) {
            #pragma unroll
            for (int d = 0; d < 6; ++d)
                gf[t][d] += __shfl_xor_sync(gmask, gf[t][d], o);
            #pragma unroll
            for (int c = 0; c < 3; ++c)
                hv[t][c] += __shfl_xor_sync(gmask, hv[t][c], o);
        }

    #pragma unroll
    for (int t = 0; t < 2; ++t) {
        float g00 = gf[t][0] + 1.f, g01 = gf[t][1], g11 = gf[t][2] + 1.f;
        float g02 = gf[t][3], g12 = gf[t][4], g22 = gf[t][5] + 1.f;
        float k00 = g11 * g22 - g12 * g12;
        float k01 = g02 * g12 - g01 * g22;
        float k02 = g01 * g12 - g02 * g11;
        float det = g00 * k00 + g01 * k01 + g02 * k02;
        float idet = 1.0f / det;
        float i00 = k00 * idet, i01 = k01 * idet, i02 = k02 * idet;
        float i11 = (g00 * g22 - g02 * g02) * idet;
        float i12 = (g01 * g02 - g00 * g12) * idet;
        float i22 = (g00 * g11 - g01 * g01) * idet;
        float h0 = hv[t][0], h1 = hv[t][1], h2 = hv[t][2];
        ac[t][0] = -0.5f * (i00 * h0 + i01 * h1 + i02 * h2);
        ac[t][1] = -0.5f * (i01 * h0 + i11 * h1 + i12 * h2);
        ac[t][2] = -0.5f * (i02 * h0 + i12 * h1 + i22 * h2);
    }
}

// ---------------------------------------------------------------------------
// Fused kernel: per-block prep (L, W into padded smem) + RK4 for 2 traj/group.
// 148 blocks x 256 threads (1 block/SM). Dense group assignment:
// blocks 0..99 handle 28 groups (7 full warps, warp 7 exits),
// blocks 100..147 handle 27 groups. Every SM runs ~7 fully-packed warps.
// ---------------------------------------------------------------------------
__global__ void __launch_bounds__(256)
geo_kernel(const float* __restrict__ pos0, const float* __restrict__ vel0,
           const float* __restrict__ beta, const float* __restrict__ ls,
           const float* __restrict__ basis, float* __restrict__ out)
{
    extern __shared__ ulonglong2 Wd[];
    __shared__ float sprm[9];
    __shared__ float red[24];

    int tid = threadIdx.x;

    // ---- L = 1.5 * max|basis| per dim ----
    {
        float m0 = 0.f, m1 = 0.f, m2 = 0.f;
        if (tid < 256) {
            m0 = fabsf(basis[tid * 3 + 0]);
            m1 = fabsf(basis[tid * 3 + 1]);
            m2 = fabsf(basis[tid * 3 + 2]);
        }
        #pragma unroll
        for (int o = 16; o > 0; o >>= 1) {
            m0 = fmaxf(m0, __shfl_xor_sync(0xffffffffu, m0, o));
            m1 = fmaxf(m1, __shfl_xor_sync(0xffffffffu, m1, o));
            m2 = fmaxf(m2, __shfl_xor_sync(0xffffffffu, m2, o));
        }
        if ((tid & 31) == 0) {
            int w = tid >> 5;
            red[w * 3 + 0] = m0; red[w * 3 + 1] = m1; red[w * 3 + 2] = m2;
        }
        __syncthreads();
        if (tid == 0) {
            #pragma unroll
            for (int d = 0; d < 3; ++d) {
                float M = 0.f;
                #pragma unroll
                for (int w = 0; w < 8; ++w) M = fmaxf(M, red[w * 3 + d]);
                float L = 1.5f * M;
                sprm[d]     = L;
                sprm[3 + d] = (float)(PI_D) / (2.0f * L);
                sprm[6 + d] = 1.0f / sqrtf(L);
            }
        }
        __syncthreads();
    }
    float L0 = sprm[0], L1 = sprm[1], L2 = sprm[2];
    float w10 = sprm[3], w11 = sprm[4], w12 = sprm[5];
    float isAll = sprm[6] * sprm[7] * sprm[8];   // folded into W below

    // ---- W into padded smem layout, normalization folded in ----
    {
        float* Wf = (float*)Wd;
        for (int idx = tid; idx < 10368; idx += 256) {
            int i2 = idx % 12;
            int d  = (idx / 12) % 6;
            int i1 = (idx / 72) % 12;
            int i0 = idx / 864;
            int m  = (i0 * 12 + i1) * 12 + i2;
            float ls0 = ls[d * 3 + 0], ls1 = ls[d * 3 + 1], ls2 = ls[d * 3 + 2];
            float q0 = w10 * (float)(i0 + 1);
            float q1 = w11 * (float)(i1 + 1);
            float q2 = w12 * (float)(i2 + 1);
            float e = -0.25f * (q0 * q0 * ls0 * ls0 + q1 * q1 * ls1 * ls1 + q2 * q2 * ls2 * ls2);
            float psd = 3.96850262992049984f * sqrtf(ls0 * ls1 * ls2) * expf(e);
            Wf[i0 * 868 + i1 * 72 + d * 12 + i2] = beta[d * 1728 + m] * psd * isAll;
        }
    }
    __syncthreads();

    // ---- dense balanced group assignment ----
    int b    = blockIdx.x;
    int cnt  = (b < 100) ? 28 : 27;
    int base = (b < 100) ? (b * 28) : (2800 + (b - 100) * 27);
    int slot = tid >> 3;
    int sub  = tid & 7;
    if (slot >= cnt) return;             // idle slots exit (after barriers)
    int group = base + slot;

    unsigned gmask = 0xFFu << ((tid & 31) & ~7);   // this 8-lane group's lanes

    int i0b = (sub >> 1) * 3;
    int i1b = (sub & 1) * 6;

    float p[2][3], v[2][3];
    #pragma unroll
    for (int t = 0; t < 2; ++t) {
        int bb = group * 2 + t;
        p[t][0] = pos0[bb * 3 + 0]; p[t][1] = pos0[bb * 3 + 1]; p[t][2] = pos0[bb * 3 + 2];
        v[t][0] = vel0[bb * 3 + 0]; v[t][1] = vel0[bb * 3 + 1]; v[t][2] = vel0[bb * 3 + 2];
    }

    if (sub == 0) {
        #pragma unroll
        for (int t = 0; t < 2; ++t) {
            int bb = group * 2 + t;
            float* op = out + (size_t)0 * NB * 3 + bb * 3;
            float* ov = out + (size_t)1 * NB * 3 + bb * 3;
            op[0] = p[t][0]; op[1] = p[t][1]; op[2] = p[t][2];
            ov[0] = v[t][0]; ov[1] = v[t][1]; ov[2] = v[t][2];
        }
    }

    const float dt  = (float)(1.0 / 49.0);
    const float hdt = (float)(0.5 * (1.0 / 49.0));
    const float dt6 = (float)((1.0 / 49.0) / 6.0);

    #pragma unroll 1
    for (int ts = 1; ts < TSTEPS; ++ts) {
        float pac[2][3], vac[2][3], dp[2][3], dv[2][3];
        #pragma unroll
        for (int t = 0; t < 2; ++t)
            #pragma unroll
            for (int c = 0; c < 3; ++c) {
                pac[t][c] = 0.f; vac[t][c] = 0.f; dp[t][c] = 0.f; dv[t][c] = 0.f;
            }
        #pragma unroll 1
        for (int s = 0; s < 4; ++s) {
            float pe[2][3], ve[2][3], ac[2][3];
            float cs = (s == 3) ? dt : hdt;
            #pragma unroll
            for (int t = 0; t < 2; ++t)
                #pragma unroll
                for (int c = 0; c < 3; ++c) {
                    if (s == 0) { pe[t][c] = p[t][c]; ve[t][c] = v[t][c]; }
                    else {
                        pe[t][c] = fmaf(cs, dp[t][c], p[t][c]);
                        ve[t][c] = fmaf(cs, dv[t][c], v[t][c]);
                    }
                }
            accel2(Wd, i0b, i1b, gmask, L0, L1, L2, w10, w11, w12,
                   pe, ve, ac);
            float w = (s == 0 || s == 3) ? 1.f : 2.f;
            #pragma unroll
            for (int t = 0; t < 2; ++t)
                #pragma unroll
                for (int c = 0; c < 3; ++c) {
                    dp[t][c] = ve[t][c]; dv[t][c] = ac[t][c];
                    pac[t][c] = fmaf(w, dp[t][c], pac[t][c]);
                    vac[t][c] = fmaf(w, dv[t][c], vac[t][c]);
                }
        }
        #pragma unroll
        for (int t = 0; t < 2; ++t)
            #pragma unroll
            for (int c = 0; c < 3; ++c) {
                p[t][c] = fmaf(dt6, pac[t][c], p[t][c]);
                v[t][c] = fmaf(dt6, vac[t][c], v[t][c]);
            }

        if (sub == 0) {
            #pragma unroll
            for (int t = 0; t < 2; ++t) {
                int bb = group * 2 + t;
                float* op = out + ((size_t)(ts * 2 + 0) * NB + bb) * 3;
                float* ov = out + ((size_t)(ts * 2 + 1) * NB + bb) * 3;
                op[0] = p[t][0]; op[1] = p[t][1]; op[2] = p[t][2];
                ov[0] = v[t][0]; ov[1] = v[t][1]; ov[2] = v[t][2];
            }
        }
    }
}

// ---------------------------------------------------------------------------
extern "C" void kernel_launch(void* const* d_in, const int* in_sizes, int n_in,
                              void* d_out, int out_size) {
    const float* pos0  = (const float*)d_in[0];
    const float* vel0  = (const float*)d_in[1];
    const float* beta  = (const float*)d_in[2];
    const float* ls    = (const float*)d_in[3];
    const float* basis = (const float*)d_in[4];
    float* out = (float*)d_out;

    geo_kernel<<<NBLK, 256, W_FLOATS * 4>>>(pos0, vel0, beta, ls, basis, out);
}